// round 4
// baseline (speedup 1.0000x reference)
#include <cuda_runtime.h>

#define NN 4096
#define FF 16
#define CM 512                   // X rows staged per chunk (32 KB smem)
#define THREADS 256
#define WARPS_PER_BLOCK 8
#define R 2                      // output rows per warp
#define ROWS_PER_BLOCK (WARPS_PER_BLOCK * R)   // 16
#define MSPLIT 2
#define MHALF (NN / MSPLIT)      // 2048 m per split

// partial results: [split][n][f]
__device__ float g_partial[MSPLIT * NN * FF];

__global__ void __launch_bounds__(THREADS, 3)
diffusion_conv_partial(const float* __restrict__ X,
                       const float* __restrict__ theta,
                       const float* __restrict__ Wp,
                       const float* __restrict__ WTp)
{
    // XOR-swizzled X chunk: float4 slot for (row ml, feature-group g) at
    // ml*4 + (g ^ ((ml>>1)&3)) — conflict-free STS.128 and LDS.128.
    __shared__ __align__(16) float4 Xs4[CM * 4];

    const int tid  = threadIdx.x;
    const int warp = tid >> 5;
    const int lane = tid & 31;

    const int n0 = blockIdx.x * ROWS_PER_BLOCK + warp * R;   // first of R rows
    const int mbase = blockIdx.y * MHALF;                    // this split's m range
    const size_t NN2 = (size_t)NN * NN;

    const float ta0 = theta[0], tb0 = theta[1];
    const float ta1 = theta[2], tb1 = theta[3];
    const float ta2 = theta[4], tb2 = theta[5];

    const float* pW0 = Wp  + (size_t)n0 * NN;
    const float* pT0 = WTp + (size_t)n0 * NN;
    const float* pW1 = pW0 + NN;
    const float* pT1 = pT0 + NN;

    float acc0[FF], acc1[FF];
#pragma unroll
    for (int f = 0; f < FF; f++) { acc0[f] = 0.0f; acc1[f] = 0.0f; }

    for (int c0 = mbase; c0 < mbase + MHALF; c0 += CM) {
        __syncthreads();   // previous chunk fully consumed

        // stage X[c0 : c0+CM][:] into swizzled smem
#pragma unroll
        for (int i = tid; i < CM; i += THREADS) {
            const float4* xr = (const float4*)(X + (size_t)(c0 + i) * FF);
            const int s = (i >> 1) & 3;
            float4 a = xr[0], b = xr[1], c = xr[2], d = xr[3];
            Xs4[i * 4 + (0 ^ s)] = a;
            Xs4[i * 4 + (1 ^ s)] = b;
            Xs4[i * 4 + (2 ^ s)] = c;
            Xs4[i * 4 + (3 ^ s)] = d;
        }
        __syncthreads();

        // sweep the chunk: lane <-> one m per step, warp covers 32 m
#pragma unroll 2
        for (int it = 0; it < CM / 32; it++) {
            const int ml = it * 32 + lane;        // chunk-local m
            const size_t gm = (size_t)(c0 + ml);  // global m

            // 12 independent scalar loads (fully coalesced per stream)
            float a00 = pW0[gm], a01 = pW0[NN2 + gm], a02 = pW0[2 * NN2 + gm];
            float b00 = pT0[gm], b01 = pT0[NN2 + gm], b02 = pT0[2 * NN2 + gm];
            float a10 = pW1[gm], a11 = pW1[NN2 + gm], a12 = pW1[2 * NN2 + gm];
            float b10 = pT1[gm], b11 = pT1[NN2 + gm], b12 = pT1[2 * NN2 + gm];

            float m0 = ta0 * a00 + ta1 * a01 + ta2 * a02
                     + tb0 * b00 + tb1 * b01 + tb2 * b02;
            float m1 = ta0 * a10 + ta1 * a11 + ta2 * a12
                     + tb0 * b10 + tb1 * b11 + tb2 * b12;

            const int sbase = ml * 4;
            const int s = (ml >> 1) & 3;
#pragma unroll
            for (int g = 0; g < 4; g++) {
                float4 xs = Xs4[sbase + (g ^ s)];   // features 4g..4g+3 of row ml
                acc0[4 * g + 0] += m0 * xs.x;  acc1[4 * g + 0] += m1 * xs.x;
                acc0[4 * g + 1] += m0 * xs.y;  acc1[4 * g + 1] += m1 * xs.y;
                acc0[4 * g + 2] += m0 * xs.z;  acc1[4 * g + 2] += m1 * xs.z;
                acc0[4 * g + 3] += m0 * xs.w;  acc1[4 * g + 3] += m1 * xs.w;
            }
        }
    }

    // cross-lane reduction
#pragma unroll
    for (int f = 0; f < FF; f++) {
#pragma unroll
        for (int d = 16; d >= 1; d >>= 1) {
            acc0[f] += __shfl_xor_sync(0xFFFFFFFFu, acc0[f], d);
            acc1[f] += __shfl_xor_sync(0xFFFFFFFFu, acc1[f], d);
        }
    }

    if (lane == 0) {
        float* p = g_partial + ((size_t)blockIdx.y * NN + n0) * FF;
#pragma unroll
        for (int f = 0; f < FF; f++) {
            p[f]      = acc0[f];
            p[FF + f] = acc1[f];
        }
    }
}

// out = X + partial[0] + partial[1], vectorized float4 (65536 floats)
__global__ void __launch_bounds__(256)
diffusion_conv_reduce(const float* __restrict__ X, float* __restrict__ out)
{
    const int i = blockIdx.x * blockDim.x + threadIdx.x;   // float4 index
    const float4* x4 = (const float4*)X;
    const float4* s0 = (const float4*)g_partial;
    const float4* s1 = (const float4*)(g_partial + NN * FF);
    float4 a = x4[i], b = s0[i], c = s1[i];
    float4 r;
    r.x = a.x + b.x + c.x;
    r.y = a.y + b.y + c.y;
    r.z = a.z + b.z + c.z;
    r.w = a.w + b.w + c.w;
    ((float4*)out)[i] = r;
}

extern "C" void kernel_launch(void* const* d_in, const int* in_sizes, int n_in,
                              void* d_out, int out_size)
{
    const float* X     = (const float*)d_in[0];   // [4096, 16]
    const float* theta = (const float*)d_in[1];   // [3, 2]
    const float* Wp    = (const float*)d_in[2];   // [3, 4096, 4096]
    const float* WTp   = (const float*)d_in[3];   // [3, 4096, 4096]
    float* out = (float*)d_out;                   // [4096, 16]

    dim3 grid(NN / ROWS_PER_BLOCK, MSPLIT);       // (256, 2) = 512 blocks
    diffusion_conv_partial<<<grid, THREADS>>>(X, theta, Wp, WTp);

    const int n4 = NN * FF / 4;                   // 16384 float4s
    diffusion_conv_reduce<<<n4 / 256, 256>>>(X, out);
}

// round 5
// speedup vs baseline: 2.4079x; 2.4079x over previous
#include <cuda_runtime.h>

#define NN 4096
#define FF 16
#define CM 512                   // X rows staged per chunk
#define XS_STRIDE (CM + 4)       // float stride per feature row in smem (pad)
#define THREADS 256
#define WARPS_PER_BLOCK 8
#define R 2                      // output rows per warp
#define ROWS_PER_BLOCK (WARPS_PER_BLOCK * R)   // 16

__global__ void __launch_bounds__(THREADS, 2)
diffusion_conv_kernel(const float* __restrict__ X,
                      const float* __restrict__ theta,
                      const float* __restrict__ Wp,
                      const float* __restrict__ WTp,
                      float* __restrict__ out)
{
    // X chunk, transposed: Xs[f][m_local], padded rows -> conflict-free LDS.128
    __shared__ __align__(16) float Xs[FF * XS_STRIDE];

    const int tid  = threadIdx.x;
    const int warp = tid >> 5;
    const int lane = tid & 31;

    const int n0 = blockIdx.x * ROWS_PER_BLOCK + warp * R;   // first of 2 rows
    const size_t NN2 = (size_t)NN * NN;

    const float ta0 = theta[0], tb0 = theta[1];
    const float ta1 = theta[2], tb1 = theta[3];
    const float ta2 = theta[4], tb2 = theta[5];

    // float4 row pointers for the 12 streams (6 per output row)
    const float4* w00 = (const float4*)(Wp  + 0 * NN2 + (size_t)n0 * NN);
    const float4* w01 = (const float4*)(Wp  + 1 * NN2 + (size_t)n0 * NN);
    const float4* w02 = (const float4*)(Wp  + 2 * NN2 + (size_t)n0 * NN);
    const float4* v00 = (const float4*)(WTp + 0 * NN2 + (size_t)n0 * NN);
    const float4* v01 = (const float4*)(WTp + 1 * NN2 + (size_t)n0 * NN);
    const float4* v02 = (const float4*)(WTp + 2 * NN2 + (size_t)n0 * NN);
    const float4* w10 = w00 + NN / 4;
    const float4* w11 = w01 + NN / 4;
    const float4* w12 = w02 + NN / 4;
    const float4* v10 = v00 + NN / 4;
    const float4* v11 = v01 + NN / 4;
    const float4* v12 = v02 + NN / 4;

    float acc0[FF], acc1[FF];
#pragma unroll
    for (int f = 0; f < FF; f++) { acc0[f] = 0.0f; acc1[f] = 0.0f; }

    for (int c0 = 0; c0 < NN; c0 += CM) {
        __syncthreads();   // previous chunk fully consumed

        // stage X[c0 : c0+CM][:] transposed into Xs[f][m_local]
        for (int i = tid; i < CM; i += THREADS) {
            const float4* xr = (const float4*)(X + (size_t)(c0 + i) * FF);
            float4 a = xr[0], b = xr[1], c = xr[2], d = xr[3];
            Xs[ 0 * XS_STRIDE + i] = a.x;  Xs[ 1 * XS_STRIDE + i] = a.y;
            Xs[ 2 * XS_STRIDE + i] = a.z;  Xs[ 3 * XS_STRIDE + i] = a.w;
            Xs[ 4 * XS_STRIDE + i] = b.x;  Xs[ 5 * XS_STRIDE + i] = b.y;
            Xs[ 6 * XS_STRIDE + i] = b.z;  Xs[ 7 * XS_STRIDE + i] = b.w;
            Xs[ 8 * XS_STRIDE + i] = c.x;  Xs[ 9 * XS_STRIDE + i] = c.y;
            Xs[10 * XS_STRIDE + i] = c.z;  Xs[11 * XS_STRIDE + i] = c.w;
            Xs[12 * XS_STRIDE + i] = d.x;  Xs[13 * XS_STRIDE + i] = d.y;
            Xs[14 * XS_STRIDE + i] = d.z;  Xs[15 * XS_STRIDE + i] = d.w;
        }
        __syncthreads();

        // warp sweeps the chunk: each lane owns 4 consecutive m per step,
        // warp covers 128 m for BOTH rows per step (X reused across rows)
#pragma unroll 1
        for (int it = 0; it < CM / 128; it++) {
            const int moff = it * 128 + 4 * lane;     // chunk-local m
            const int gidx = (c0 + moff) >> 2;        // float4 index in row

            // 12 independent LDG.128 (6 KB in flight per warp)
            float4 a00 = w00[gidx], a01 = w01[gidx], a02 = w02[gidx];
            float4 b00 = v00[gidx], b01 = v01[gidx], b02 = v02[gidx];
            float4 a10 = w10[gidx], a11 = w11[gidx], a12 = w12[gidx];
            float4 b10 = v10[gidx], b11 = v11[gidx], b12 = v12[gidx];

            float4 M0, M1;
            M0.x = ta0 * a00.x + ta1 * a01.x + ta2 * a02.x
                 + tb0 * b00.x + tb1 * b01.x + tb2 * b02.x;
            M0.y = ta0 * a00.y + ta1 * a01.y + ta2 * a02.y
                 + tb0 * b00.y + tb1 * b01.y + tb2 * b02.y;
            M0.z = ta0 * a00.z + ta1 * a01.z + ta2 * a02.z
                 + tb0 * b00.z + tb1 * b01.z + tb2 * b02.z;
            M0.w = ta0 * a00.w + ta1 * a01.w + ta2 * a02.w
                 + tb0 * b00.w + tb1 * b01.w + tb2 * b02.w;
            M1.x = ta0 * a10.x + ta1 * a11.x + ta2 * a12.x
                 + tb0 * b10.x + tb1 * b11.x + tb2 * b12.x;
            M1.y = ta0 * a10.y + ta1 * a11.y + ta2 * a12.y
                 + tb0 * b10.y + tb1 * b11.y + tb2 * b12.y;
            M1.z = ta0 * a10.z + ta1 * a11.z + ta2 * a12.z
                 + tb0 * b10.z + tb1 * b11.z + tb2 * b12.z;
            M1.w = ta0 * a10.w + ta1 * a11.w + ta2 * a12.w
                 + tb0 * b10.w + tb1 * b11.w + tb2 * b12.w;

#pragma unroll
            for (int f = 0; f < FF; f++) {
                float4 xs = *(const float4*)&Xs[f * XS_STRIDE + moff];
                acc0[f] += M0.x * xs.x + M0.y * xs.y
                         + M0.z * xs.z + M0.w * xs.w;
                acc1[f] += M1.x * xs.x + M1.y * xs.y
                         + M1.z * xs.z + M1.w * xs.w;
            }
        }
    }

    // butterfly-reduce each feature across the warp
#pragma unroll
    for (int f = 0; f < FF; f++) {
#pragma unroll
        for (int d = 16; d >= 1; d >>= 1) {
            acc0[f] += __shfl_xor_sync(0xFFFFFFFFu, acc0[f], d);
            acc1[f] += __shfl_xor_sync(0xFFFFFFFFu, acc1[f], d);
        }
    }

    if (lane == 0) {
        const float* x0 = X + (size_t)n0 * FF;
        float* o0 = out + (size_t)n0 * FF;
#pragma unroll
        for (int f = 0; f < FF; f++) {
            o0[f]      = x0[f]      + acc0[f];
            o0[FF + f] = x0[FF + f] + acc1[f];
        }
    }
}

extern "C" void kernel_launch(void* const* d_in, const int* in_sizes, int n_in,
                              void* d_out, int out_size)
{
    const float* X     = (const float*)d_in[0];   // [4096, 16]
    const float* theta = (const float*)d_in[1];   // [3, 2]
    const float* Wp    = (const float*)d_in[2];   // [3, 4096, 4096]
    const float* WTp   = (const float*)d_in[3];   // [3, 4096, 4096]
    float* out = (float*)d_out;                   // [4096, 16]

    dim3 grid(NN / ROWS_PER_BLOCK);               // 256 blocks
    dim3 block(THREADS);
    diffusion_conv_kernel<<<grid, block>>>(X, theta, Wp, WTp, out);
}